// round 1
// baseline (speedup 1.0000x reference)
#include <cuda_runtime.h>
#include <cuda_bf16.h>
#include <math_constants.h>

// Problem constants (fixed by the reference):
//   inputs:     [64,32,32,64] f32  -> N = 65536 rows, D = 64
//   embeddings: [64,512]      f32  -> D = 64, K = 512
// Outputs (assumed flattened concat, f32):
//   quantized [N*64] | indices [N] (as float) | loss [1]
#define N_ROWS    65536
#define DIM       64
#define KCODES    512
#define ROWS_BLK  128
#define CODE_BLK  128
#define THREADS   256

#define XS_STRIDE 132          // padded row stride for transposed X tile (floats)
#define SMEM_XS   (DIM * XS_STRIDE)          // 8448 floats
#define SMEM_ES   (DIM * CODE_BLK)           // 8192 floats
#define SMEM_EN   (KCODES)                   // 512 floats
#define SMEM_FLOATS (SMEM_XS + SMEM_ES + SMEM_EN)
#define SMEM_BYTES (SMEM_FLOATS * 4)

#define Q_ELEMS   ((size_t)N_ROWS * DIM)     // 4194304
#define IDX_OFF   Q_ELEMS
#define LOSS_OFF  (Q_ELEMS + N_ROWS)

__device__ float g_enorm[KCODES];
__device__ float g_partials[N_ROWS / ROWS_BLK];   // 512 block partial loss sums

// ---------------------------------------------------------------------------
// Kernel 1: per-code squared norms
// ---------------------------------------------------------------------------
__global__ void vq_enorm_kernel(const float* __restrict__ E) {
    int k = threadIdx.x;
    if (k < KCODES) {
        float s = 0.f;
        #pragma unroll
        for (int d = 0; d < DIM; ++d) {
            float v = E[d * KCODES + k];
            s = fmaf(v, v, s);
        }
        g_enorm[k] = s;
    }
}

// ---------------------------------------------------------------------------
// Kernel 2: main GEMM + argmin + gather + partial loss
// grid = 512 blocks (128 rows each), 256 threads
// ---------------------------------------------------------------------------
__global__ void __launch_bounds__(THREADS)
vq_main_kernel(const float* __restrict__ X, const float* __restrict__ E,
               float* __restrict__ out, int out_size) {
    extern __shared__ float smem[];
    float* Xs      = smem;                   // [DIM][XS_STRIDE], transposed X tile
    float* Es      = Xs + SMEM_XS;           // [DIM][CODE_BLK]
    float* enorm_s = Es + SMEM_ES;           // [KCODES]

    const int t  = threadIdx.x;
    const int tx = t & 15;                   // code group   (8 codes)
    const int ty = t >> 4;                   // row group    (8 rows)
    const int rowBase = blockIdx.x * ROWS_BLK;

    // ---- load X tile, transposed into Xs[d][row] ----
    {
        const int lr = t >> 4;               // 0..15 local row per pass
        const int dv = (t & 15) * 4;         // 0..60
        #pragma unroll
        for (int it = 0; it < 8; ++it) {
            int row = it * 16 + lr;
            float4 v = *reinterpret_cast<const float4*>(
                X + (size_t)(rowBase + row) * DIM + dv);
            Xs[(dv + 0) * XS_STRIDE + row] = v.x;
            Xs[(dv + 1) * XS_STRIDE + row] = v.y;
            Xs[(dv + 2) * XS_STRIDE + row] = v.z;
            Xs[(dv + 3) * XS_STRIDE + row] = v.w;
        }
        for (int i = t; i < KCODES; i += THREADS) enorm_s[i] = g_enorm[i];
    }

    float bestv[8];
    int   besti[8];
    #pragma unroll
    for (int i = 0; i < 8; ++i) { bestv[i] = CUDART_INF_F; besti[i] = 0; }

    // ---- loop over 4 code chunks of 128 ----
    for (int c0 = 0; c0 < KCODES; c0 += CODE_BLK) {
        __syncthreads();   // previous chunk's Es reads complete
        // load Es[d][c] chunk: coalesced in global (stride-512 rows)
        for (int i = t; i < DIM * (CODE_BLK / 4); i += THREADS) {
            int d  = i >> 5;           // /32
            int cv = (i & 31) * 4;
            float4 v = *reinterpret_cast<const float4*>(
                E + (size_t)d * KCODES + c0 + cv);
            *reinterpret_cast<float4*>(&Es[d * CODE_BLK + cv]) = v;
        }
        __syncthreads();

        float acc[8][8];
        #pragma unroll
        for (int i = 0; i < 8; ++i)
            #pragma unroll
            for (int j = 0; j < 8; ++j) acc[i][j] = 0.f;

        #pragma unroll 4
        for (int d = 0; d < DIM; ++d) {
            float4 xa = *reinterpret_cast<const float4*>(&Xs[d * XS_STRIDE + 8 * ty]);
            float4 xb = *reinterpret_cast<const float4*>(&Xs[d * XS_STRIDE + 8 * ty + 4]);
            float4 ea = *reinterpret_cast<const float4*>(&Es[d * CODE_BLK + 8 * tx]);
            float4 eb = *reinterpret_cast<const float4*>(&Es[d * CODE_BLK + 8 * tx + 4]);
            float xr[8] = {xa.x, xa.y, xa.z, xa.w, xb.x, xb.y, xb.z, xb.w};
            float er[8] = {ea.x, ea.y, ea.z, ea.w, eb.x, eb.y, eb.z, eb.w};
            #pragma unroll
            for (int i = 0; i < 8; ++i)
                #pragma unroll
                for (int j = 0; j < 8; ++j)
                    acc[i][j] = fmaf(xr[i], er[j], acc[i][j]);
        }

        // running argmin over this chunk (||x||^2 dropped: constant per row)
        #pragma unroll
        for (int j = 0; j < 8; ++j) {
            int code = c0 + 8 * tx + j;
            float en = enorm_s[code];
            #pragma unroll
            for (int i = 0; i < 8; ++i) {
                float v = fmaf(-2.f, acc[i][j], en);
                if (v < bestv[i]) { bestv[i] = v; besti[i] = code; }
            }
        }
    }

    // ---- cross-thread argmin reduction (16 candidates per row) ----
    __syncthreads();
    // reuse Es region: redv[128*17] floats, redi[128*17] ints, rowcode[128]
    float* redv   = Es;
    int*   redi   = reinterpret_cast<int*>(Es + ROWS_BLK * 17);
    int*   rowcode = reinterpret_cast<int*>(Es + ROWS_BLK * 17) + ROWS_BLK * 17;
    #pragma unroll
    for (int i = 0; i < 8; ++i) {
        int row = 8 * ty + i;
        redv[row * 17 + tx] = bestv[i];
        redi[row * 17 + tx] = besti[i];
    }
    __syncthreads();
    if (t < ROWS_BLK) {
        float bv = redv[t * 17];
        int   bi = redi[t * 17];
        #pragma unroll
        for (int k = 1; k < 16; ++k) {               // ascending tx = ascending code
            float v = redv[t * 17 + k];
            int   i = redi[t * 17 + k];
            if (v < bv) { bv = v; bi = i; }
        }
        rowcode[t] = bi;
        size_t ipos = IDX_OFF + (size_t)(rowBase + t);
        if (ipos < (size_t)out_size) out[ipos] = (float)bi;
    }
    __syncthreads();

    // ---- gather quantized, write out, accumulate loss ----
    float lsum = 0.f;
    for (int i = t; i < ROWS_BLK * DIM; i += THREADS) {
        int r = i >> 6, d = i & 63;
        int code = rowcode[r];
        float q = E[(size_t)d * KCODES + code];
        float x = Xs[d * XS_STRIDE + r];
        out[(size_t)(rowBase + r) * DIM + d] = q;
        float df = q - x;
        lsum = fmaf(df, df, lsum);
    }

    // deterministic block reduction of lsum (fixed tree)
    __syncthreads();
    float* red = Xs;           // Xs no longer needed
    red[t] = lsum;
    __syncthreads();
    #pragma unroll
    for (int s = THREADS / 2; s > 0; s >>= 1) {
        if (t < s) red[t] += red[t + s];
        __syncthreads();
    }
    if (t == 0) g_partials[blockIdx.x] = red[0];
}

// ---------------------------------------------------------------------------
// Kernel 3: deterministic final loss reduction
// ---------------------------------------------------------------------------
__global__ void vq_finalize_kernel(float* __restrict__ out, int out_size) {
    if (threadIdx.x == 0 && blockIdx.x == 0) {
        float s = 0.f;
        #pragma unroll 8
        for (int i = 0; i < N_ROWS / ROWS_BLK; ++i) s += g_partials[i];
        float loss = 1.25f * s / (float)Q_ELEMS;
        if (LOSS_OFF < (size_t)out_size) out[LOSS_OFF] = loss;
    }
}

// ---------------------------------------------------------------------------
extern "C" void kernel_launch(void* const* d_in, const int* in_sizes, int n_in,
                              void* d_out, int out_size) {
    // robust input identification: embeddings has 64*512 = 32768 elements
    const float* X;
    const float* E;
    if (in_sizes[0] == DIM * KCODES && in_sizes[1] != DIM * KCODES) {
        E = (const float*)d_in[0];
        X = (const float*)d_in[1];
    } else {
        X = (const float*)d_in[0];
        E = (const float*)d_in[1];
    }
    float* out = (float*)d_out;

    static bool attr_done = false;
    if (!attr_done) {
        cudaFuncSetAttribute(vq_main_kernel,
                             cudaFuncAttributeMaxDynamicSharedMemorySize, SMEM_BYTES);
        attr_done = true;
    }

    vq_enorm_kernel<<<1, KCODES>>>(E);
    vq_main_kernel<<<N_ROWS / ROWS_BLK, THREADS, SMEM_BYTES>>>(X, E, out, out_size);
    vq_finalize_kernel<<<1, 32>>>(out, out_size);
}

// round 5
// speedup vs baseline: 1.5572x; 1.5572x over previous
#include <cuda_runtime.h>
#include <cuda_bf16.h>
#include <math_constants.h>

typedef unsigned int u32;

// Problem: inputs [64,32,32,64] f32 -> N=65536 rows, D=64; embeddings [64,512] f32.
// Output (f32 concat): quantized [N*64] | indices [N] | loss [1]
#define N_ROWS   65536
#define DIM      64
#define KCODES   512
#define ROWS_BLK 128
#define CHUNK    64
#define NCHUNKS  (KCODES / CHUNK)        // 8
#define THREADS  256
#define NBLOCKS  (N_ROWS / ROWS_BLK)     // 512

#define Q_ELEMS  ((size_t)N_ROWS * DIM)
#define IDX_OFF  Q_ELEMS
#define LOSS_OFF (Q_ELEMS + N_ROWS)

// SMEM layout (bytes). Stride 144 = 128B row + 16B pad -> LDSM conflict-free.
#define ASTRIDE   144
#define OFF_A_HI  0
#define OFF_A_LO  (OFF_A_HI + ROWS_BLK * ASTRIDE)     // 18432
#define OFF_B_HI  (OFF_A_LO + ROWS_BLK * ASTRIDE)     // 36864
#define OFF_B_LO  (OFF_B_HI + CHUNK * ASTRIDE)        // 46080
#define OFF_ENORM (OFF_B_LO + CHUNK * ASTRIDE)        // 55296
#define OFF_ROWCODE (OFF_ENORM + KCODES * 4)          // 57344
#define SMEM_TOTAL  (OFF_ROWCODE + ROWS_BLK * 4)      // 57856

#define REFINE_THRESH 1e-3f

__device__ float         g_enorm[KCODES];
__device__ float         g_partials[NBLOCKS];
__device__ __nv_bfloat16 g_Ebh[KCODES * DIM];   // [code][d] bf16 hi
__device__ __nv_bfloat16 g_Ebl[KCODES * DIM];   // [code][d] bf16 lo

// ---------------------------------------------------------------------------
static __device__ __forceinline__ u32 smem_u32(const void* p) {
    u32 a;
    asm("{ .reg .u64 t; cvta.to.shared.u64 t, %1; cvt.u32.u64 %0, t; }" : "=r"(a) : "l"(p));
    return a;
}
static __device__ __forceinline__ void ldsm_x4(u32& r0, u32& r1, u32& r2, u32& r3, u32 a) {
    asm volatile("ldmatrix.sync.aligned.m8n8.x4.shared.b16 {%0,%1,%2,%3}, [%4];"
                 : "=r"(r0), "=r"(r1), "=r"(r2), "=r"(r3) : "r"(a));
}
static __device__ __forceinline__ void ldsm_x2(u32& r0, u32& r1, u32 a) {
    asm volatile("ldmatrix.sync.aligned.m8n8.x2.shared.b16 {%0,%1}, [%2];"
                 : "=r"(r0), "=r"(r1) : "r"(a));
}
static __device__ __forceinline__ void mma_bf16(float* c, u32 a0, u32 a1, u32 a2, u32 a3,
                                                u32 b0, u32 b1) {
    asm volatile("mma.sync.aligned.m16n8k16.row.col.f32.bf16.bf16.f32 "
                 "{%0,%1,%2,%3}, {%4,%5,%6,%7}, {%8,%9}, {%0,%1,%2,%3};"
                 : "+f"(c[0]), "+f"(c[1]), "+f"(c[2]), "+f"(c[3])
                 : "r"(a0), "r"(a1), "r"(a2), "r"(a3), "r"(b0), "r"(b1));
}

// ---------------------------------------------------------------------------
// Kernel 1: prep — enorm + bf16 hi/lo embeddings in [code][d] layout
// ---------------------------------------------------------------------------
__global__ void vq_prep_kernel(const float* __restrict__ E) {
    int gid  = blockIdx.x * 512 + threadIdx.x;      // 0..32767
    int code = gid >> 6;
    int d    = gid & 63;
    float v  = E[(size_t)d * KCODES + code];
    __nv_bfloat16 hi = __float2bfloat16_rn(v);
    __nv_bfloat16 lo = __float2bfloat16_rn(v - __bfloat162float(hi));
    g_Ebh[gid] = hi;
    g_Ebl[gid] = lo;
    if (gid < KCODES) {
        float s = 0.f;
        #pragma unroll
        for (int dd = 0; dd < DIM; ++dd) {
            float e = E[(size_t)dd * KCODES + gid];
            s = fmaf(e, e, s);
        }
        g_enorm[gid] = s;
    }
}

// ---------------------------------------------------------------------------
// Kernel 2: main — bf16 mma.sync 3-split GEMM + argmin + refine + gather/loss
// ---------------------------------------------------------------------------
static __device__ __forceinline__ float exact_dist(const float* __restrict__ xr,
                                                   const float* __restrict__ E,
                                                   const float* __restrict__ enorm_s,
                                                   int code) {
    float dot = 0.f;
    #pragma unroll
    for (int d = 0; d < DIM; ++d)
        dot = fmaf(xr[d], E[(size_t)d * KCODES + code], dot);
    return fmaf(-2.f, dot, enorm_s[code]);
}

__global__ void __launch_bounds__(THREADS)
vq_main_kernel(const float* __restrict__ X, const float* __restrict__ E,
               float* __restrict__ out, int out_size) {
    extern __shared__ char smem[];
    const u32 sb   = smem_u32(smem);
    const int tid  = threadIdx.x;
    const int lane = tid & 31;
    const int warp = tid >> 5;
    const int rowBase = blockIdx.x * ROWS_BLK;
    const int warpRow = warp * 16;

    float* enorm_s = reinterpret_cast<float*>(smem + OFF_ENORM);
    int*   rowcode = reinterpret_cast<int*>(smem + OFF_ROWCODE);

    // ---- load enorm + A tile (fp32 -> bf16 hi/lo, stride-144 rows) ----
    for (int i = tid; i < KCODES; i += THREADS) enorm_s[i] = g_enorm[i];

    #pragma unroll
    for (int it = 0; it < 4; ++it) {
        int task = tid + THREADS * it;          // 1024 tasks: 128 rows x 8 groups
        int r  = task >> 3;
        int d0 = (task & 7) * 8;
        const float4* xv = reinterpret_cast<const float4*>(
            X + (size_t)(rowBase + r) * DIM + d0);
        float4 v0 = xv[0], v1 = xv[1];
        float vals[8] = {v0.x, v0.y, v0.z, v0.w, v1.x, v1.y, v1.z, v1.w};
        union { __nv_bfloat16 h[8]; uint4 u; } ph, pl;
        #pragma unroll
        for (int e = 0; e < 8; ++e) {
            ph.h[e] = __float2bfloat16_rn(vals[e]);
            pl.h[e] = __float2bfloat16_rn(vals[e] - __bfloat162float(ph.h[e]));
        }
        u32 off = (u32)(r * ASTRIDE + d0 * 2);
        *reinterpret_cast<uint4*>(smem + OFF_A_HI + off) = ph.u;
        *reinterpret_cast<uint4*>(smem + OFF_A_LO + off) = pl.u;
    }

    // ldmatrix base addresses
    const int mA = lane >> 3, rA = lane & 7;
    const u32 aHiBase = sb + OFF_A_HI + (u32)((warpRow + (mA & 1) * 8 + rA) * ASTRIDE
                                              + (mA >> 1) * 16);
    const u32 aLoBase = aHiBase + (OFF_A_LO - OFF_A_HI);
    const u32 bHiBase = sb + OFF_B_HI + (u32)((lane & 7) * ASTRIDE + ((lane >> 3) & 1) * 16);
    const u32 bLoBase = bHiBase + (OFF_B_LO - OFF_B_HI);

    // top-2 state, two rows per thread (rowA = warpRow+q, rowB = +8)
    float b1a = CUDART_INF_F, b2a = CUDART_INF_F;
    float b1b = CUDART_INF_F, b2b = CUDART_INF_F;
    int   i1a = 0, i2a = 0, i1b = 0, i2b = 0;

    for (int ch = 0; ch < NCHUNKS; ++ch) {
        const int c0 = ch * CHUNK;
        __syncthreads();          // previous chunk's B reads complete
        // stage B chunk (both splits): 64 codes x 64 bf16 each
        {
            const uint4* gh = reinterpret_cast<const uint4*>(g_Ebh + (size_t)c0 * DIM);
            const uint4* gl = reinterpret_cast<const uint4*>(g_Ebl + (size_t)c0 * DIM);
            for (int i = tid; i < CHUNK * 8; i += THREADS) {
                int r = i >> 3, q = i & 7;
                *reinterpret_cast<uint4*>(smem + OFF_B_HI + r * ASTRIDE + q * 16) = gh[i];
                *reinterpret_cast<uint4*>(smem + OFF_B_LO + r * ASTRIDE + q * 16) = gl[i];
            }
        }
        __syncthreads();

        float acc[8][4];
        #pragma unroll
        for (int nt = 0; nt < 8; ++nt)
            #pragma unroll
            for (int j = 0; j < 4; ++j) acc[nt][j] = 0.f;

        // pass 1: (A_hi + A_lo) x B_hi  — B fragment reused for both splits
        #pragma unroll
        for (int ks = 0; ks < 4; ++ks) {
            u32 ah0, ah1, ah2, ah3, al0, al1, al2, al3;
            ldsm_x4(ah0, ah1, ah2, ah3, aHiBase + ks * 32);
            ldsm_x4(al0, al1, al2, al3, aLoBase + ks * 32);
            #pragma unroll
            for (int nt = 0; nt < 8; ++nt) {
                u32 b0, b1;
                ldsm_x2(b0, b1, bHiBase + nt * (8 * ASTRIDE) + ks * 32);
                mma_bf16(acc[nt], ah0, ah1, ah2, ah3, b0, b1);
                mma_bf16(acc[nt], al0, al1, al2, al3, b0, b1);
            }
        }
        // pass 2: A_hi x B_lo
        #pragma unroll
        for (int ks = 0; ks < 4; ++ks) {
            u32 ah0, ah1, ah2, ah3;
            ldsm_x4(ah0, ah1, ah2, ah3, aHiBase + ks * 32);
            #pragma unroll
            for (int nt = 0; nt < 8; ++nt) {
                u32 b0, b1;
                ldsm_x2(b0, b1, bLoBase + nt * (8 * ASTRIDE) + ks * 32);
                mma_bf16(acc[nt], ah0, ah1, ah2, ah3, b0, b1);
            }
        }

        // running top-2 argmin over this chunk (codes ascend -> lowest-index wins ties)
        const int colBase = 2 * (lane & 3);
        #pragma unroll
        for (int nt = 0; nt < 8; ++nt) {
            int   code0 = c0 + nt * 8 + colBase;
            float e0 = enorm_s[code0], e1 = enorm_s[code0 + 1];
            float v;
            #define UPD(B1, I1, B2, I2, VAL, IDX)                        \
                do { v = (VAL);                                          \
                     bool p = v < B1; bool q2 = v < B2;                  \
                     float t = fmaxf(v, B1);                             \
                     B2 = fminf(B2, t);                                  \
                     I2 = q2 ? (p ? I1 : (IDX)) : I2;                    \
                     B1 = fminf(B1, v);                                  \
                     I1 = p ? (IDX) : I1; } while (0)
            UPD(b1a, i1a, b2a, i2a, fmaf(-2.f, acc[nt][0], e0), code0);
            UPD(b1a, i1a, b2a, i2a, fmaf(-2.f, acc[nt][1], e1), code0 + 1);
            UPD(b1b, i1b, b2b, i2b, fmaf(-2.f, acc[nt][2], e0), code0);
            UPD(b1b, i1b, b2b, i2b, fmaf(-2.f, acc[nt][3], e1), code0 + 1);
            #undef UPD
        }
    }

    // ---- cross-lane top-2 merge within each quad (lanes differing in bits 0-1) ----
    #define MERGE(B1, I1, B2, I2, OFFX)                                           \
        do {                                                                      \
            float o1 = __shfl_xor_sync(0xffffffffu, B1, OFFX);                    \
            int  oi1 = __shfl_xor_sync(0xffffffffu, I1, OFFX);                    \
            float o2 = __shfl_xor_sync(0xffffffffu, B2, OFFX);                    \
            int  oi2 = __shfl_xor_sync(0xffffffffu, I2, OFFX);                    \
            bool t1 = (o1 < B1) || (o1 == B1 && oi1 < I1);                        \
            float l1 = t1 ? B1 : o1;  int li1 = t1 ? I1 : oi1;                    \
            float s2 = t1 ? o2 : B2;  int si2 = t1 ? oi2 : I2;                    \
            bool t2 = (l1 < s2) || (l1 == s2 && li1 < si2);                       \
            B1 = t1 ? o1 : B1;  I1 = t1 ? oi1 : I1;                               \
            B2 = t2 ? l1 : s2;  I2 = t2 ? li1 : si2;                              \
        } while (0)
    MERGE(b1a, i1a, b2a, i2a, 1);
    MERGE(b1a, i1a, b2a, i2a, 2);
    MERGE(b1b, i1b, b2b, i2b, 1);
    MERGE(b1b, i1b, b2b, i2b, 2);
    #undef MERGE

    if ((lane & 3) == 0) {
        int q = lane >> 2;
        int rA = warpRow + q;
        int rB = warpRow + q + 8;
        // rare exact-fp32 refine of near-ties
        if (b2a - b1a < REFINE_THRESH) {
            const float* xr = X + (size_t)(rowBase + rA) * DIM;
            float d1 = exact_dist(xr, E, enorm_s, i1a);
            float d2 = exact_dist(xr, E, enorm_s, i2a);
            if (d2 < d1 || (d2 == d1 && i2a < i1a)) i1a = i2a;
        }
        if (b2b - b1b < REFINE_THRESH) {
            const float* xr = X + (size_t)(rowBase + rB) * DIM;
            float d1 = exact_dist(xr, E, enorm_s, i1b);
            float d2 = exact_dist(xr, E, enorm_s, i2b);
            if (d2 < d1 || (d2 == d1 && i2b < i1b)) i1b = i2b;
        }
        rowcode[rA] = i1a;
        rowcode[rB] = i1b;
        size_t pA = IDX_OFF + (size_t)(rowBase + rA);
        size_t pB = IDX_OFF + (size_t)(rowBase + rB);
        if (pA < (size_t)out_size) out[pA] = (float)i1a;
        if (pB < (size_t)out_size) out[pB] = (float)i1b;
    }
    __syncthreads();

    // ---- gather quantized (fp32 E), write out, partial loss ----
    float lsum = 0.f;
    for (int i = tid; i < ROWS_BLK * DIM; i += THREADS) {
        int r = i >> 6, d = i & 63;
        int code = rowcode[r];
        float qv = E[(size_t)d * KCODES + code];
        float xv = X[(size_t)(rowBase + r) * DIM + d];
        out[(size_t)(rowBase + r) * DIM + d] = qv;
        float df = qv - xv;
        lsum = fmaf(df, df, lsum);
    }

    __syncthreads();
    float* red = reinterpret_cast<float*>(smem + OFF_A_HI);   // A dead now
    red[tid] = lsum;
    __syncthreads();
    #pragma unroll
    for (int s = THREADS / 2; s > 0; s >>= 1) {
        if (tid < s) red[tid] += red[tid + s];
        __syncthreads();
    }
    if (tid == 0) g_partials[blockIdx.x] = red[0];
}

// ---------------------------------------------------------------------------
// Kernel 3: deterministic final loss reduction
// ---------------------------------------------------------------------------
__global__ void vq_finalize_kernel(float* __restrict__ out, int out_size) {
    if (threadIdx.x == 0 && blockIdx.x == 0) {
        float s = 0.f;
        #pragma unroll 8
        for (int i = 0; i < NBLOCKS; ++i) s += g_partials[i];
        float loss = 1.25f * s / (float)Q_ELEMS;
        if (LOSS_OFF < (size_t)out_size) out[LOSS_OFF] = loss;
    }
}

// ---------------------------------------------------------------------------
extern "C" void kernel_launch(void* const* d_in, const int* in_sizes, int n_in,
                              void* d_out, int out_size) {
    const float* X;
    const float* E;
    if (in_sizes[0] == DIM * KCODES && in_sizes[1] != DIM * KCODES) {
        E = (const float*)d_in[0];
        X = (const float*)d_in[1];
    } else {
        X = (const float*)d_in[0];
        E = (const float*)d_in[1];
    }
    float* out = (float*)d_out;

    static bool attr_done = false;
    if (!attr_done) {
        cudaFuncSetAttribute(vq_main_kernel,
                             cudaFuncAttributeMaxDynamicSharedMemorySize, SMEM_TOTAL);
        attr_done = true;
    }

    vq_prep_kernel<<<64, 512>>>(E);
    vq_main_kernel<<<NBLOCKS, THREADS, SMEM_TOTAL>>>(X, E, out, out_size);
    vq_finalize_kernel<<<1, 32>>>(out, out_size);
}